// round 16
// baseline (speedup 1.0000x reference)
#include <cuda_runtime.h>
#include <cuda_bf16.h>
#include <cstdint>

#define NN 50000
#define CC 128
#define NE 800000
#define NAUTH 2000
#define NSMALL 65
#define NBLK ((NN + 1023) / 1024)   // 49 scan blocks
#define MROWS ((NN + 127) / 128)    // 391
#define MITERS 4
#define GROUPS ((MROWS + MITERS - 1) / MITERS)  // 98

// ---------------- scratch (device globals; allocation-free rule) ----------------
__device__ float  g_dinv[NN];
__device__ int    g_cnt[NN];
__device__ int    g_scan[NN];
__device__ int    g_bsum[64];
__device__ int    g_rowptr[NN + 1];
__device__ int    g_cursor[NN];
__device__ int    g_col[NE];
__device__ float4 g_h[NN * 32];              // dense transform [NN][128]
__device__ __nv_bfloat16 g_AH[NN * 128];     // A operand hi (x, relu(h1), emb)
__device__ __nv_bfloat16 g_AL[NN * 128];     // A operand lo
__device__ __nv_bfloat16 g_WaH[NAUTH * 128]; // Wa^T [n][k]
__device__ __nv_bfloat16 g_WaL[NAUTH * 128];
__device__ __nv_bfloat16 g_W1H[128 * 128];
__device__ __nv_bfloat16 g_W1L[128 * 128];
__device__ __nv_bfloat16 g_W2H[128 * 128];
__device__ __nv_bfloat16 g_W2L[128 * 128];
__device__ __nv_bfloat16 g_WsmH[NSMALL * 128];
__device__ __nv_bfloat16 g_WsmL[NSMALL * 128];
__device__ float g_Csmall[NN * NSMALL];

// ---------------- CSR build ----------------
__global__ void zero_cnt_kernel() {
    int i = blockIdx.x * blockDim.x + threadIdx.x;
    if (i < NN) g_cnt[i] = 0;
}
__global__ void cnt_accum_kernel(const int* __restrict__ ei) {
    int e = blockIdx.x * blockDim.x + threadIdx.x;
    if (e < NE) atomicAdd(&g_cnt[ei[e]], 1);
}
__global__ void scan1_kernel() {
    int tid = threadIdx.x;
    int i = blockIdx.x * 1024 + tid;
    int lane = tid & 31, wid = tid >> 5;
    int v = (i < NN) ? g_cnt[i] : 0;
    int s = v;
#pragma unroll
    for (int o = 1; o < 32; o <<= 1) {
        int t = __shfl_up_sync(0xFFFFFFFFu, s, o);
        if (lane >= o) s += t;
    }
    __shared__ int wsum[32];
    if (lane == 31) wsum[wid] = s;
    __syncthreads();
    if (wid == 0) {
        int w = wsum[lane];
#pragma unroll
        for (int o = 1; o < 32; o <<= 1) {
            int t = __shfl_up_sync(0xFFFFFFFFu, w, o);
            if (lane >= o) w += t;
        }
        wsum[lane] = w;
    }
    __syncthreads();
    int inc = s + (wid > 0 ? wsum[wid - 1] : 0);
    if (i < NN) g_scan[i] = inc;
    if (tid == 1023) g_bsum[blockIdx.x] = inc;
}
__global__ void scan2_kernel() {
    __shared__ int s[64];
    int tid = threadIdx.x;
    s[tid] = (tid < NBLK) ? g_bsum[tid] : 0;
    __syncthreads();
    if (tid == 0) {
        int a = 0;
        for (int b = 0; b < NBLK; b++) { int t = s[b]; s[b] = a; a += t; }
    }
    __syncthreads();
    if (tid < NBLK) g_bsum[tid] = s[tid];
}
__global__ void scan3_kernel() {
    int i = blockIdx.x * blockDim.x + threadIdx.x;
    if (i >= NN) return;
    int ex = g_scan[i] - g_cnt[i] + g_bsum[i >> 10];
    g_rowptr[i] = ex;
    g_cursor[i] = ex;
    g_dinv[i] = rsqrtf((float)(g_cnt[i] + 1));
    if (i == 0) g_rowptr[NN] = NE;
}
__global__ void scatter_edges_kernel(const int* __restrict__ ei) {
    int e = blockIdx.x * blockDim.x + threadIdx.x;
    if (e >= NE) return;
    int r = ei[e], c = ei[NE + e];
    int pos = atomicAdd(&g_cursor[r], 1);
    g_col[pos] = c;
}

// ---------------- fused CSR aggregation + bias (+relu) + bf16 hi/lo ----------------
// warp per node; lanes pre-load 32 edges' col/dinv coalesced, shfl-broadcast,
// 4-way unrolled gathers for MLP.
template <int RELU>
__global__ void csr_agg_kernel(const float* __restrict__ bias) {
    int w = (blockIdx.x * blockDim.x + threadIdx.x) >> 5;
    int lane = threadIdx.x & 31;
    if (w >= NN) return;
    int s = g_rowptr[w], t = g_rowptr[w + 1];
    float dd = g_dinv[w];
    float sc = dd * dd;
    float4 acc = g_h[(size_t)w * 32 + lane];
    acc.x *= sc; acc.y *= sc; acc.z *= sc; acc.w *= sc;

    for (int base = s; base < t; base += 32) {
        int cnt = t - base;
        if (cnt > 32) cnt = 32;
        int c_l = 0;
        float nm_l = 0.f;
        if (lane < cnt) {
            c_l = g_col[base + lane];            // coalesced
            nm_l = dd * g_dinv[c_l];             // MLP across lanes
        }
        int j = 0;
        for (; j + 4 <= cnt; j += 4) {
            int c0 = __shfl_sync(0xFFFFFFFFu, c_l, j + 0);
            int c1 = __shfl_sync(0xFFFFFFFFu, c_l, j + 1);
            int c2 = __shfl_sync(0xFFFFFFFFu, c_l, j + 2);
            int c3 = __shfl_sync(0xFFFFFFFFu, c_l, j + 3);
            float n0 = __shfl_sync(0xFFFFFFFFu, nm_l, j + 0);
            float n1 = __shfl_sync(0xFFFFFFFFu, nm_l, j + 1);
            float n2 = __shfl_sync(0xFFFFFFFFu, nm_l, j + 2);
            float n3 = __shfl_sync(0xFFFFFFFFu, nm_l, j + 3);
            float4 v0 = g_h[(size_t)c0 * 32 + lane];
            float4 v1 = g_h[(size_t)c1 * 32 + lane];
            float4 v2 = g_h[(size_t)c2 * 32 + lane];
            float4 v3 = g_h[(size_t)c3 * 32 + lane];
            acc.x += v0.x * n0; acc.y += v0.y * n0; acc.z += v0.z * n0; acc.w += v0.w * n0;
            acc.x += v1.x * n1; acc.y += v1.y * n1; acc.z += v1.z * n1; acc.w += v1.w * n1;
            acc.x += v2.x * n2; acc.y += v2.y * n2; acc.z += v2.z * n2; acc.w += v2.w * n2;
            acc.x += v3.x * n3; acc.y += v3.y * n3; acc.z += v3.z * n3; acc.w += v3.w * n3;
        }
        for (; j < cnt; j++) {
            int c = __shfl_sync(0xFFFFFFFFu, c_l, j);
            float nm = __shfl_sync(0xFFFFFFFFu, nm_l, j);
            float4 v = g_h[(size_t)c * 32 + lane];
            acc.x += v.x * nm; acc.y += v.y * nm; acc.z += v.z * nm; acc.w += v.w * nm;
        }
    }

    float4 b = ((const float4*)bias)[lane];
    acc.x += b.x; acc.y += b.y; acc.z += b.z; acc.w += b.w;
    if (RELU) {
        acc.x = fmaxf(acc.x, 0.f); acc.y = fmaxf(acc.y, 0.f);
        acc.z = fmaxf(acc.z, 0.f); acc.w = fmaxf(acc.w, 0.f);
    }
    float f[4] = {acc.x, acc.y, acc.z, acc.w};
    __nv_bfloat16 hi[4], lo[4];
#pragma unroll
    for (int q = 0; q < 4; q++) {
        hi[q] = __float2bfloat16(f[q]);
        lo[q] = __float2bfloat16(f[q] - __bfloat162float(hi[q]));
    }
    size_t idx = ((size_t)w * 32 + lane) * 4;
    *(uint2*)(g_AH + idx) = *(uint2*)hi;
    *(uint2*)(g_AL + idx) = *(uint2*)lo;
}

// ---------------- conversions ----------------
__global__ void convert_x_kernel(const float* __restrict__ x) {
    int i = blockIdx.x * blockDim.x + threadIdx.x;
    if (i >= NN * 32) return;
    float4 v = ((const float4*)x)[i];
    float f[4] = {v.x, v.y, v.z, v.w};
    __nv_bfloat16 hi[4], lo[4];
#pragma unroll
    for (int q = 0; q < 4; q++) {
        hi[q] = __float2bfloat16(f[q]);
        lo[q] = __float2bfloat16(f[q] - __bfloat162float(hi[q]));
    }
    *(uint2*)(g_AH + (size_t)i * 4) = *(uint2*)hi;
    *(uint2*)(g_AL + (size_t)i * 4) = *(uint2*)lo;
}
__global__ void convert_W_kernel(const float* __restrict__ W, int N,
                                 __nv_bfloat16* __restrict__ dH, __nv_bfloat16* __restrict__ dL) {
    int i = blockIdx.x * blockDim.x + threadIdx.x;
    if (i >= N * 128) return;
    int n = i >> 7, k = i & 127;
    float f = W[(size_t)k * N + n];
    __nv_bfloat16 hi = __float2bfloat16(f);
    dH[i] = hi;
    dL[i] = __float2bfloat16(f - __bfloat162float(hi));
}
__global__ void pack_small_kernel(const float* __restrict__ Wt, const float* __restrict__ Ws,
                                  const float* __restrict__ Wf) {
    int i = blockIdx.x * blockDim.x + threadIdx.x;
    if (i >= NSMALL * 128) return;
    int j = i >> 7, k = i & 127;
    float v;
    if (j < 30)      v = Wt[(size_t)k * 30 + j];
    else if (j < 50) v = Ws[(size_t)k * 20 + (j - 30)];
    else             v = Wf[(size_t)k * 15 + (j - 50)];
    __nv_bfloat16 hi = __float2bfloat16(v);
    g_WsmH[i] = hi;
    g_WsmL[i] = __float2bfloat16(v - __bfloat162float(hi));
}
__global__ void split_small_kernel(const float* __restrict__ bt, const float* __restrict__ bs,
                                   const float* __restrict__ bfb, float* __restrict__ out) {
    int i = blockIdx.x * blockDim.x + threadIdx.x;
    if (i >= NN * NSMALL) return;
    int m = i / NSMALL, j = i % NSMALL;
    float v = g_Csmall[i];
    if (j < 30)      out[(size_t)m * 30 + j] = v + bt[j];
    else if (j < 50) out[(size_t)NN * 30 + (size_t)m * 20 + (j - 30)] = v + bs[j - 30];
    else             out[(size_t)NN * 50 + (size_t)m * 15 + (j - 50)] = v + bfb[j - 50];
}

// ---------------- mma common ----------------
#define TSTRIDE 136
#define TILE_BYTES (128 * TSTRIDE * 2)   // 34816

__device__ __forceinline__ uint32_t smem_u32(const void* p) {
    uint32_t a;
    asm("{ .reg .u64 t; cvta.to.shared.u64 t, %1; cvt.u32.u64 %0, t; }" : "=r"(a) : "l"(p));
    return a;
}
__device__ __forceinline__ void ldsm_x4(uint32_t* r, uint32_t addr) {
    asm volatile("ldmatrix.sync.aligned.m8n8.x4.shared.b16 {%0,%1,%2,%3}, [%4];"
                 : "=r"(r[0]), "=r"(r[1]), "=r"(r[2]), "=r"(r[3]) : "r"(addr));
}
__device__ __forceinline__ void mma_bf16(float* d, const uint32_t* a, const uint32_t* b) {
    asm volatile(
        "mma.sync.aligned.m16n8k16.row.col.f32.bf16.bf16.f32 "
        "{%0,%1,%2,%3}, {%4,%5,%6,%7}, {%8,%9}, {%0,%1,%2,%3};"
        : "+f"(d[0]), "+f"(d[1]), "+f"(d[2]), "+f"(d[3])
        : "r"(a[0]), "r"(a[1]), "r"(a[2]), "r"(a[3]), "r"(b[0]), "r"(b[1]));
}
__device__ __forceinline__ void cp_async16(uint32_t dst, const void* src) {
    asm volatile("cp.async.cg.shared.global [%0], [%1], 16;" :: "r"(dst), "l"(src));
}
#define CP_COMMIT() asm volatile("cp.async.commit_group;" ::: "memory")
#define CP_WAIT0()  asm volatile("cp.async.wait_group 0;" ::: "memory")

__device__ __forceinline__ void load_tile_bf16(char* dst, const __nv_bfloat16* __restrict__ src,
                                               int row0, int rowmax, int tid) {
    for (int i = tid; i < 2048; i += 256) {
        int r = i >> 4;
        int k = (i & 15) << 3;
        int gr = row0 + r;
        uint4 v = make_uint4(0, 0, 0, 0);
        if (gr < rowmax) v = *(const uint4*)(src + (size_t)gr * 128 + k);
        *(uint4*)(dst + ((size_t)r * TSTRIDE + k) * 2) = v;
    }
}
__device__ __forceinline__ void load_tile_async(uint32_t dst, const __nv_bfloat16* __restrict__ src,
                                                int row0, int rowmax, int tid) {
    for (int i = tid; i < 2048; i += 256) {
        int r = i >> 4;
        int k = (i & 15) << 3;
        int gr = row0 + r;
        if (gr >= rowmax) gr = rowmax - 1;
        cp_async16(dst + (uint32_t)(r * TSTRIDE + k) * 2, src + (size_t)gr * 128 + k);
    }
}

__device__ __forceinline__ void mma_tile_compute_store(
    uint32_t aHi, uint32_t aLo, uint32_t bHi, uint32_t bLo,
    const float* __restrict__ bias, float* __restrict__ outp,
    int bm, int bn, int M, int NOUT, int wid, int lane)
{
    const int wm = (wid & 3) * 32;
    const int wn = (wid >> 2) * 64;
    float acc[2][8][4];
#pragma unroll
    for (int mt = 0; mt < 2; mt++)
#pragma unroll
        for (int nt = 0; nt < 8; nt++)
#pragma unroll
            for (int q = 0; q < 4; q++) acc[mt][nt][q] = 0.f;

    const uint32_t aBase[3] = { aHi, aHi, aLo };
    const uint32_t bBase[3] = { bHi, bLo, bHi };
    const int a_row = wm + (lane & 15);
    const int a_col8 = (lane >> 4) * 8;
    const int b_row = wn + (lane & 7) + ((lane >> 4) & 1) * 8;
    const int b_col8 = ((lane >> 3) & 1) * 8;

#pragma unroll
    for (int p = 0; p < 3; p++) {
        const uint32_t ab = aBase[p];
        const uint32_t bb = bBase[p];
#pragma unroll
        for (int ks = 0; ks < 8; ks++) {
            uint32_t afr[2][4];
#pragma unroll
            for (int mt = 0; mt < 2; mt++) {
                uint32_t addr = ab + (uint32_t)(((a_row + mt * 16) * TSTRIDE) + ks * 16 + a_col8) * 2;
                ldsm_x4(afr[mt], addr);
            }
            uint32_t bfr[8][2];
#pragma unroll
            for (int np = 0; np < 4; np++) {
                uint32_t r[4];
                uint32_t addr = bb + (uint32_t)(((b_row + np * 16) * TSTRIDE) + ks * 16 + b_col8) * 2;
                ldsm_x4(r, addr);
                bfr[2 * np][0] = r[0]; bfr[2 * np][1] = r[1];
                bfr[2 * np + 1][0] = r[2]; bfr[2 * np + 1][1] = r[3];
            }
#pragma unroll
            for (int mt = 0; mt < 2; mt++)
#pragma unroll
                for (int nt = 0; nt < 8; nt++)
                    mma_bf16(acc[mt][nt], afr[mt], bfr[nt]);
        }
    }

    const bool vec2 = ((NOUT & 1) == 0);
    const int g = lane >> 2, t = lane & 3;
#pragma unroll
    for (int mt = 0; mt < 2; mt++) {
        int m0 = bm + wm + mt * 16 + g;
#pragma unroll
        for (int nt = 0; nt < 8; nt++) {
            int n0 = bn + wn + nt * 8 + t * 2;
            if (n0 >= NOUT) continue;
            float bx = bias ? bias[n0] : 0.f;
            bool has2 = (n0 + 1 < NOUT);
            float by = (bias && has2) ? bias[n0 + 1] : 0.f;
            if (m0 < M) {
                float* p = outp + (size_t)m0 * NOUT + n0;
                if (has2 && vec2) *(float2*)p = make_float2(acc[mt][nt][0] + bx, acc[mt][nt][1] + by);
                else { p[0] = acc[mt][nt][0] + bx; if (has2) p[1] = acc[mt][nt][1] + by; }
            }
            if (m0 + 8 < M) {
                float* p = outp + (size_t)(m0 + 8) * NOUT + n0;
                if (has2 && vec2) *(float2*)p = make_float2(acc[mt][nt][2] + bx, acc[mt][nt][3] + by);
                else { p[0] = acc[mt][nt][2] + bx; if (has2) p[1] = acc[mt][nt][3] + by; }
            }
        }
    }
}

// ---------------- generic single-tile mma GEMM (layers + small heads) ----------------
__global__ __launch_bounds__(256) void mma_gemm_kernel(
    const __nv_bfloat16* __restrict__ AH, const __nv_bfloat16* __restrict__ AL,
    const __nv_bfloat16* __restrict__ BH, const __nv_bfloat16* __restrict__ BL,
    const float* __restrict__ bias, float* __restrict__ outp, int M, int NOUT)
{
    extern __shared__ char smem[];
    char* sAh = smem;
    char* sAl = smem + TILE_BYTES;
    char* sBh = smem + 2 * TILE_BYTES;
    char* sBl = smem + 3 * TILE_BYTES;
    const int tid = threadIdx.x, wid = tid >> 5, lane = tid & 31;
    const int bm = blockIdx.y * 128;
    const int bn = blockIdx.x * 128;
    load_tile_bf16(sAh, AH, bm, M, tid);
    load_tile_bf16(sAl, AL, bm, M, tid);
    load_tile_bf16(sBh, BH, bn, NOUT, tid);
    load_tile_bf16(sBl, BL, bn, NOUT, tid);
    __syncthreads();
    mma_tile_compute_store(smem_u32(sAh), smem_u32(sAl), smem_u32(sBh), smem_u32(sBl),
                           bias, outp, bm, bn, M, NOUT, wid, lane);
}

// ---------------- author head: B-resident, cp.async double-buffered A ----------------
#define ASM_TOTAL (6 * TILE_BYTES)

__global__ __launch_bounds__(256) void author_mma_kernel(
    const __nv_bfloat16* __restrict__ AH, const __nv_bfloat16* __restrict__ AL,
    const __nv_bfloat16* __restrict__ BH, const __nv_bfloat16* __restrict__ BL,
    const float* __restrict__ bias, float* __restrict__ outp, int M, int NOUT)
{
    extern __shared__ char smem[];
    uint32_t sb = smem_u32(smem);
    const int tid = threadIdx.x, wid = tid >> 5, lane = tid & 31;
    const int bn = blockIdx.x * 128;
    const int mt0 = blockIdx.y * MITERS;

    const uint32_t sBh = sb;
    const uint32_t sBl = sb + TILE_BYTES;
    const uint32_t sA0 = sb + 2 * TILE_BYTES;
    const uint32_t sA1 = sb + 4 * TILE_BYTES;

    load_tile_async(sBh, BH, bn, NOUT, tid);
    load_tile_async(sBl, BL, bn, NOUT, tid);
    int bm0 = mt0 * 128;
    if (bm0 < M) {
        load_tile_async(sA0, AH, bm0, M, tid);
        load_tile_async(sA0 + TILE_BYTES, AL, bm0, M, tid);
    }
    CP_COMMIT();

    int buf = 0;
#pragma unroll 1
    for (int it = 0; it < MITERS; it++) {
        int bm = (mt0 + it) * 128;
        if (bm >= M) break;
        CP_WAIT0();
        __syncthreads();
        int bmn = (mt0 + it + 1) * 128;
        if (it + 1 < MITERS && bmn < M) {
            uint32_t nb = (buf ^ 1) ? sA1 : sA0;
            load_tile_async(nb, AH, bmn, M, tid);
            load_tile_async(nb + TILE_BYTES, AL, bmn, M, tid);
        }
        CP_COMMIT();
        uint32_t cb = buf ? sA1 : sA0;
        mma_tile_compute_store(cb, cb + TILE_BYTES, sBh, sBl,
                               bias, outp, bm, bn, M, NOUT, wid, lane);
        buf ^= 1;
    }
}

// ---------------- launch ----------------
extern "C" void kernel_launch(void* const* d_in, const int* in_sizes, int n_in,
                              void* d_out, int out_size) {
    const float* x  = (const float*)d_in[0];
    const int*   ei = (const int*)d_in[1];   // [2, NE] int32
    const float* W1 = (const float*)d_in[2];
    const float* b1 = (const float*)d_in[3];
    const float* W2 = (const float*)d_in[4];
    const float* b2 = (const float*)d_in[5];
    const float* Wt = (const float*)d_in[6];
    const float* bt = (const float*)d_in[7];
    const float* Ws = (const float*)d_in[8];
    const float* bs = (const float*)d_in[9];
    const float* Wf = (const float*)d_in[10];
    const float* bfb = (const float*)d_in[11];
    const float* Wa = (const float*)d_in[12];
    const float* ba = (const float*)d_in[13];
    float* out = (float*)d_out;

    float4* h4;
    float* csmall;
    __nv_bfloat16 *aH, *aL, *w1H, *w1L, *w2H, *w2L, *waH, *waL, *wsH, *wsL;
    cudaGetSymbolAddress((void**)&h4, g_h);
    cudaGetSymbolAddress((void**)&csmall, g_Csmall);
    cudaGetSymbolAddress((void**)&aH, g_AH);
    cudaGetSymbolAddress((void**)&aL, g_AL);
    cudaGetSymbolAddress((void**)&w1H, g_W1H);
    cudaGetSymbolAddress((void**)&w1L, g_W1L);
    cudaGetSymbolAddress((void**)&w2H, g_W2H);
    cudaGetSymbolAddress((void**)&w2L, g_W2L);
    cudaGetSymbolAddress((void**)&waH, g_WaH);
    cudaGetSymbolAddress((void**)&waL, g_WaL);
    cudaGetSymbolAddress((void**)&wsH, g_WsmH);
    cudaGetSymbolAddress((void**)&wsL, g_WsmL);

    static cudaStream_t s1;
    static cudaEvent_t evA, evW1, evB, evW2, evWa, evC, evD;
    static bool init0 = false;
    if (!init0) {
        cudaFuncSetAttribute(mma_gemm_kernel,
                             cudaFuncAttributeMaxDynamicSharedMemorySize, 4 * TILE_BYTES);
        cudaFuncSetAttribute(author_mma_kernel,
                             cudaFuncAttributeMaxDynamicSharedMemorySize, ASM_TOTAL);
        cudaStreamCreateWithFlags(&s1, cudaStreamNonBlocking);
        cudaEventCreateWithFlags(&evA,  cudaEventDisableTiming);
        cudaEventCreateWithFlags(&evW1, cudaEventDisableTiming);
        cudaEventCreateWithFlags(&evB,  cudaEventDisableTiming);
        cudaEventCreateWithFlags(&evW2, cudaEventDisableTiming);
        cudaEventCreateWithFlags(&evWa, cudaEventDisableTiming);
        cudaEventCreateWithFlags(&evC,  cudaEventDisableTiming);
        cudaEventCreateWithFlags(&evD,  cudaEventDisableTiming);
        init0 = true;
    }

    // ---- fork: s1 handles W conversions + CSR build ----
    cudaEventRecord(evA, 0);
    cudaStreamWaitEvent(s1, evA, 0);
    convert_W_kernel<<<(128 * 128 + 255) / 256, 256, 0, s1>>>(W1, 128, w1H, w1L);
    cudaEventRecord(evW1, s1);
    zero_cnt_kernel<<<(NN + 255) / 256, 256, 0, s1>>>();
    cnt_accum_kernel<<<(NE + 255) / 256, 256, 0, s1>>>(ei);
    scan1_kernel<<<NBLK, 1024, 0, s1>>>();
    scan2_kernel<<<1, 64, 0, s1>>>();
    scan3_kernel<<<(NN + 255) / 256, 256, 0, s1>>>();
    scatter_edges_kernel<<<(NE + 255) / 256, 256, 0, s1>>>(ei);
    cudaEventRecord(evB, s1);
    convert_W_kernel<<<(128 * 128 + 255) / 256, 256, 0, s1>>>(W2, 128, w2H, w2L);
    cudaEventRecord(evW2, s1);
    convert_W_kernel<<<(NAUTH * 128 + 255) / 256, 256, 0, s1>>>(Wa, NAUTH, waH, waL);
    pack_small_kernel<<<(NSMALL * 128 + 255) / 256, 256, 0, s1>>>(Wt, Ws, Wf);
    cudaEventRecord(evWa, s1);

    const int AGG_BLK = (NN * 32 + 255) / 256;

    // ---- main stream ----
    convert_x_kernel<<<(NN * 32 + 255) / 256, 256>>>(x);
    cudaStreamWaitEvent(0, evW1, 0);
    mma_gemm_kernel<<<dim3(1, MROWS), 256, 4 * TILE_BYTES>>>(aH, aL, w1H, w1L, nullptr,
                                                             (float*)h4, NN, 128);
    cudaStreamWaitEvent(0, evB, 0);
    csr_agg_kernel<1><<<AGG_BLK, 256>>>(b1);

    cudaStreamWaitEvent(0, evW2, 0);
    mma_gemm_kernel<<<dim3(1, MROWS), 256, 4 * TILE_BYTES>>>(aH, aL, w2H, w2L, nullptr,
                                                             (float*)h4, NN, 128);
    csr_agg_kernel<0><<<AGG_BLK, 256>>>(b2);

    // ---- fork: small heads on s1, concurrent with author head ----
    cudaEventRecord(evC, 0);
    cudaStreamWaitEvent(s1, evC, 0);
    mma_gemm_kernel<<<dim3(1, MROWS), 256, 4 * TILE_BYTES, s1>>>(aH, aL, wsH, wsL, nullptr,
                                                                 csmall, NN, NSMALL);
    split_small_kernel<<<(NN * NSMALL + 255) / 256, 256, 0, s1>>>(bt, bs, bfb, out);
    cudaEventRecord(evD, s1);

    // author head (main stream)
    cudaStreamWaitEvent(0, evWa, 0);
    author_mma_kernel<<<dim3(16, GROUPS), 256, ASM_TOTAL>>>(
        aH, aL, waH, waL, ba, out + (size_t)NN * 65, NN, NAUTH);
    cudaStreamWaitEvent(0, evD, 0);
}

// round 17
// speedup vs baseline: 1.5344x; 1.5344x over previous
#include <cuda_runtime.h>
#include <cuda_fp16.h>
#include <cstdint>

#define NN 50000
#define CC 128
#define NE 800000
#define NAUTH 2000
#define NSMALL 65
#define NBLK ((NN + 1023) / 1024)   // 49 scan blocks
#define MROWS ((NN + 127) / 128)    // 391
#define MITERS 4
#define GROUPS ((MROWS + MITERS - 1) / MITERS)  // 98

// ---------------- scratch (device globals; allocation-free rule) ----------------
__device__ float  g_dinv[NN];
__device__ int    g_cnt[NN];
__device__ int    g_scan[NN];
__device__ int    g_bsum[64];
__device__ int    g_rowptr[NN + 1];
__device__ int    g_cursor[NN];
__device__ int    g_col[NE];
__device__ float4 g_h[NN * 32];        // dense transform [NN][128]
__device__ __half g_AH[NN * 128];      // A operand hi (x, relu(h1), emb)
__device__ __half g_AL[NN * 128];      // A operand lo
__device__ __half g_WaH[NAUTH * 128];  // Wa^T [n][k]
__device__ __half g_WaL[NAUTH * 128];
__device__ __half g_W1H[128 * 128];
__device__ __half g_W1L[128 * 128];
__device__ __half g_W2H[128 * 128];
__device__ __half g_W2L[128 * 128];
__device__ __half g_WsmH[NSMALL * 128];
__device__ __half g_WsmL[NSMALL * 128];
__device__ float g_Csmall[NN * NSMALL];

// ---------------- CSR build ----------------
__global__ void zero_cnt_kernel() {
    int i = blockIdx.x * blockDim.x + threadIdx.x;
    if (i < NN) g_cnt[i] = 0;
}
__global__ void cnt_accum_kernel(const int* __restrict__ ei) {
    int e = blockIdx.x * blockDim.x + threadIdx.x;
    if (e < NE) atomicAdd(&g_cnt[ei[e]], 1);
}
__global__ void scan1_kernel() {
    int tid = threadIdx.x;
    int i = blockIdx.x * 1024 + tid;
    int lane = tid & 31, wid = tid >> 5;
    int v = (i < NN) ? g_cnt[i] : 0;
    int s = v;
#pragma unroll
    for (int o = 1; o < 32; o <<= 1) {
        int t = __shfl_up_sync(0xFFFFFFFFu, s, o);
        if (lane >= o) s += t;
    }
    __shared__ int wsum[32];
    if (lane == 31) wsum[wid] = s;
    __syncthreads();
    if (wid == 0) {
        int w = wsum[lane];
#pragma unroll
        for (int o = 1; o < 32; o <<= 1) {
            int t = __shfl_up_sync(0xFFFFFFFFu, w, o);
            if (lane >= o) w += t;
        }
        wsum[lane] = w;
    }
    __syncthreads();
    int inc = s + (wid > 0 ? wsum[wid - 1] : 0);
    if (i < NN) g_scan[i] = inc;
    if (tid == 1023) g_bsum[blockIdx.x] = inc;
}
__global__ void scan2_kernel() {
    __shared__ int s[64];
    int tid = threadIdx.x;
    s[tid] = (tid < NBLK) ? g_bsum[tid] : 0;
    __syncthreads();
    if (tid == 0) {
        int a = 0;
        for (int b = 0; b < NBLK; b++) { int t = s[b]; s[b] = a; a += t; }
    }
    __syncthreads();
    if (tid < NBLK) g_bsum[tid] = s[tid];
}
__global__ void scan3_kernel() {
    int i = blockIdx.x * blockDim.x + threadIdx.x;
    if (i >= NN) return;
    int ex = g_scan[i] - g_cnt[i] + g_bsum[i >> 10];
    g_rowptr[i] = ex;
    g_cursor[i] = ex;
    g_dinv[i] = rsqrtf((float)(g_cnt[i] + 1));
    if (i == 0) g_rowptr[NN] = NE;
}
__global__ void scatter_edges_kernel(const int* __restrict__ ei) {
    int e = blockIdx.x * blockDim.x + threadIdx.x;
    if (e >= NE) return;
    int r = ei[e], c = ei[NE + e];
    int pos = atomicAdd(&g_cursor[r], 1);
    g_col[pos] = c;
}

// ---------------- fp16 hi/lo helper ----------------
__device__ __forceinline__ void split_h(float f, __half& hi, __half& lo) {
    hi = __float2half(f);
    lo = __float2half(f - __half2float(hi));
}

// ---------------- fused CSR aggregation + bias (+relu) + fp16 hi/lo ----------------
template <int RELU>
__global__ void csr_agg_kernel(const float* __restrict__ bias) {
    int w = (blockIdx.x * blockDim.x + threadIdx.x) >> 5;
    int lane = threadIdx.x & 31;
    if (w >= NN) return;
    int s = g_rowptr[w], t = g_rowptr[w + 1];
    float dd = g_dinv[w];
    float sc = dd * dd;
    float4 acc = g_h[(size_t)w * 32 + lane];
    acc.x *= sc; acc.y *= sc; acc.z *= sc; acc.w *= sc;

    for (int base = s; base < t; base += 32) {
        int cnt = t - base;
        if (cnt > 32) cnt = 32;
        int c_l = 0;
        float nm_l = 0.f;
        if (lane < cnt) {
            c_l = g_col[base + lane];
            nm_l = dd * g_dinv[c_l];
        }
        int j = 0;
        for (; j + 4 <= cnt; j += 4) {
            int c0 = __shfl_sync(0xFFFFFFFFu, c_l, j + 0);
            int c1 = __shfl_sync(0xFFFFFFFFu, c_l, j + 1);
            int c2 = __shfl_sync(0xFFFFFFFFu, c_l, j + 2);
            int c3 = __shfl_sync(0xFFFFFFFFu, c_l, j + 3);
            float n0 = __shfl_sync(0xFFFFFFFFu, nm_l, j + 0);
            float n1 = __shfl_sync(0xFFFFFFFFu, nm_l, j + 1);
            float n2 = __shfl_sync(0xFFFFFFFFu, nm_l, j + 2);
            float n3 = __shfl_sync(0xFFFFFFFFu, nm_l, j + 3);
            float4 v0 = g_h[(size_t)c0 * 32 + lane];
            float4 v1 = g_h[(size_t)c1 * 32 + lane];
            float4 v2 = g_h[(size_t)c2 * 32 + lane];
            float4 v3 = g_h[(size_t)c3 * 32 + lane];
            acc.x += v0.x * n0; acc.y += v0.y * n0; acc.z += v0.z * n0; acc.w += v0.w * n0;
            acc.x += v1.x * n1; acc.y += v1.y * n1; acc.z += v1.z * n1; acc.w += v1.w * n1;
            acc.x += v2.x * n2; acc.y += v2.y * n2; acc.z += v2.z * n2; acc.w += v2.w * n2;
            acc.x += v3.x * n3; acc.y += v3.y * n3; acc.z += v3.z * n3; acc.w += v3.w * n3;
        }
        for (; j < cnt; j++) {
            int c = __shfl_sync(0xFFFFFFFFu, c_l, j);
            float nm = __shfl_sync(0xFFFFFFFFu, nm_l, j);
            float4 v = g_h[(size_t)c * 32 + lane];
            acc.x += v.x * nm; acc.y += v.y * nm; acc.z += v.z * nm; acc.w += v.w * nm;
        }
    }

    float4 b = ((const float4*)bias)[lane];
    acc.x += b.x; acc.y += b.y; acc.z += b.z; acc.w += b.w;
    if (RELU) {
        acc.x = fmaxf(acc.x, 0.f); acc.y = fmaxf(acc.y, 0.f);
        acc.z = fmaxf(acc.z, 0.f); acc.w = fmaxf(acc.w, 0.f);
    }
    float f[4] = {acc.x, acc.y, acc.z, acc.w};
    __half hi[4], lo[4];
#pragma unroll
    for (int q = 0; q < 4; q++) split_h(f[q], hi[q], lo[q]);
    size_t idx = ((size_t)w * 32 + lane) * 4;
    *(uint2*)(g_AH + idx) = *(uint2*)hi;
    *(uint2*)(g_AL + idx) = *(uint2*)lo;
}

// ---------------- conversions ----------------
__global__ void convert_x_kernel(const float* __restrict__ x) {
    int i = blockIdx.x * blockDim.x + threadIdx.x;
    if (i >= NN * 32) return;
    float4 v = ((const float4*)x)[i];
    float f[4] = {v.x, v.y, v.z, v.w};
    __half hi[4], lo[4];
#pragma unroll
    for (int q = 0; q < 4; q++) split_h(f[q], hi[q], lo[q]);
    *(uint2*)(g_AH + (size_t)i * 4) = *(uint2*)hi;
    *(uint2*)(g_AL + (size_t)i * 4) = *(uint2*)lo;
}
__global__ void convert_W_kernel(const float* __restrict__ W, int N,
                                 __half* __restrict__ dH, __half* __restrict__ dL) {
    int i = blockIdx.x * blockDim.x + threadIdx.x;
    if (i >= N * 128) return;
    int n = i >> 7, k = i & 127;
    __half hi, lo;
    split_h(W[(size_t)k * N + n], hi, lo);
    dH[i] = hi;
    dL[i] = lo;
}
__global__ void pack_small_kernel(const float* __restrict__ Wt, const float* __restrict__ Ws,
                                  const float* __restrict__ Wf) {
    int i = blockIdx.x * blockDim.x + threadIdx.x;
    if (i >= NSMALL * 128) return;
    int j = i >> 7, k = i & 127;
    float v;
    if (j < 30)      v = Wt[(size_t)k * 30 + j];
    else if (j < 50) v = Ws[(size_t)k * 20 + (j - 30)];
    else             v = Wf[(size_t)k * 15 + (j - 50)];
    __half hi, lo;
    split_h(v, hi, lo);
    g_WsmH[i] = hi;
    g_WsmL[i] = lo;
}
__global__ void split_small_kernel(const float* __restrict__ bt, const float* __restrict__ bs,
                                   const float* __restrict__ bfb, float* __restrict__ out) {
    int i = blockIdx.x * blockDim.x + threadIdx.x;
    if (i >= NN * NSMALL) return;
    int m = i / NSMALL, j = i % NSMALL;
    float v = g_Csmall[i];
    if (j < 30)      out[(size_t)m * 30 + j] = v + bt[j];
    else if (j < 50) out[(size_t)NN * 30 + (size_t)m * 20 + (j - 30)] = v + bs[j - 30];
    else             out[(size_t)NN * 50 + (size_t)m * 15 + (j - 50)] = v + bfb[j - 50];
}

// ---------------- mma common ----------------
#define TSTRIDE 136
#define TILE_BYTES (128 * TSTRIDE * 2)   // 34816

__device__ __forceinline__ uint32_t smem_u32(const void* p) {
    uint32_t a;
    asm("{ .reg .u64 t; cvta.to.shared.u64 t, %1; cvt.u32.u64 %0, t; }" : "=r"(a) : "l"(p));
    return a;
}
__device__ __forceinline__ void ldsm_x4(uint32_t* r, uint32_t addr) {
    asm volatile("ldmatrix.sync.aligned.m8n8.x4.shared.b16 {%0,%1,%2,%3}, [%4];"
                 : "=r"(r[0]), "=r"(r[1]), "=r"(r[2]), "=r"(r[3]) : "r"(addr));
}
__device__ __forceinline__ void mma_f16(float* d, const uint32_t* a, const uint32_t* b) {
    asm volatile(
        "mma.sync.aligned.m16n8k16.row.col.f32.f16.f16.f32 "
        "{%0,%1,%2,%3}, {%4,%5,%6,%7}, {%8,%9}, {%0,%1,%2,%3};"
        : "+f"(d[0]), "+f"(d[1]), "+f"(d[2]), "+f"(d[3])
        : "r"(a[0]), "r"(a[1]), "r"(a[2]), "r"(a[3]), "r"(b[0]), "r"(b[1]));
}
__device__ __forceinline__ void cp_async16(uint32_t dst, const void* src) {
    asm volatile("cp.async.cg.shared.global [%0], [%1], 16;" :: "r"(dst), "l"(src));
}
#define CP_COMMIT() asm volatile("cp.async.commit_group;" ::: "memory")
#define CP_WAIT0()  asm volatile("cp.async.wait_group 0;" ::: "memory")

__device__ __forceinline__ void load_tile_f16(char* dst, const __half* __restrict__ src,
                                              int row0, int rowmax, int tid) {
    for (int i = tid; i < 2048; i += 256) {
        int r = i >> 4;
        int k = (i & 15) << 3;
        int gr = row0 + r;
        uint4 v = make_uint4(0, 0, 0, 0);
        if (gr < rowmax) v = *(const uint4*)(src + (size_t)gr * 128 + k);
        *(uint4*)(dst + ((size_t)r * TSTRIDE + k) * 2) = v;
    }
}
__device__ __forceinline__ void load_tile_async(uint32_t dst, const __half* __restrict__ src,
                                                int row0, int rowmax, int tid) {
    for (int i = tid; i < 2048; i += 256) {
        int r = i >> 4;
        int k = (i & 15) << 3;
        int gr = row0 + r;
        if (gr >= rowmax) gr = rowmax - 1;
        cp_async16(dst + (uint32_t)(r * TSTRIDE + k) * 2, src + (size_t)gr * 128 + k);
    }
}

// 2-pass fp16 hi/lo: Ah*Bh + Ah*Bl (Al*Bh dropped; fp16 residual ~2^-12.8)
__device__ __forceinline__ void mma_tile_compute_store(
    uint32_t aHi, uint32_t bHi, uint32_t bLo,
    const float* __restrict__ bias, float* __restrict__ outp,
    int bm, int bn, int M, int NOUT, int wid, int lane)
{
    const int wm = (wid & 3) * 32;
    const int wn = (wid >> 2) * 64;
    float acc[2][8][4];
#pragma unroll
    for (int mt = 0; mt < 2; mt++)
#pragma unroll
        for (int nt = 0; nt < 8; nt++)
#pragma unroll
            for (int q = 0; q < 4; q++) acc[mt][nt][q] = 0.f;

    const uint32_t bBase[2] = { bHi, bLo };
    const int a_row = wm + (lane & 15);
    const int a_col8 = (lane >> 4) * 8;
    const int b_row = wn + (lane & 7) + ((lane >> 4) & 1) * 8;
    const int b_col8 = ((lane >> 3) & 1) * 8;

#pragma unroll
    for (int p = 0; p < 2; p++) {
        const uint32_t ab = aHi;
        const uint32_t bb = bBase[p];
#pragma unroll
        for (int ks = 0; ks < 8; ks++) {
            uint32_t afr[2][4];
#pragma unroll
            for (int mt = 0; mt < 2; mt++) {
                uint32_t addr = ab + (uint32_t)(((a_row + mt * 16) * TSTRIDE) + ks * 16 + a_col8) * 2;
                ldsm_x4(afr[mt], addr);
            }
            uint32_t bfr[8][2];
#pragma unroll
            for (int np = 0; np < 4; np++) {
                uint32_t r[4];
                uint32_t addr = bb + (uint32_t)(((b_row + np * 16) * TSTRIDE) + ks * 16 + b_col8) * 2;
                ldsm_x4(r, addr);
                bfr[2 * np][0] = r[0]; bfr[2 * np][1] = r[1];
                bfr[2 * np + 1][0] = r[2]; bfr[2 * np + 1][1] = r[3];
            }
#pragma unroll
            for (int mt = 0; mt < 2; mt++)
#pragma unroll
                for (int nt = 0; nt < 8; nt++)
                    mma_f16(acc[mt][nt], afr[mt], bfr[nt]);
        }
    }

    const bool vec2 = ((NOUT & 1) == 0);
    const int g = lane >> 2, t = lane & 3;
#pragma unroll
    for (int mt = 0; mt < 2; mt++) {
        int m0 = bm + wm + mt * 16 + g;
#pragma unroll
        for (int nt = 0; nt < 8; nt++) {
            int n0 = bn + wn + nt * 8 + t * 2;
            if (n0 >= NOUT) continue;
            float bx = bias ? bias[n0] : 0.f;
            bool has2 = (n0 + 1 < NOUT);
            float by = (bias && has2) ? bias[n0 + 1] : 0.f;
            if (m0 < M) {
                float* p = outp + (size_t)m0 * NOUT + n0;
                if (has2 && vec2) *(float2*)p = make_float2(acc[mt][nt][0] + bx, acc[mt][nt][1] + by);
                else { p[0] = acc[mt][nt][0] + bx; if (has2) p[1] = acc[mt][nt][1] + by; }
            }
            if (m0 + 8 < M) {
                float* p = outp + (size_t)(m0 + 8) * NOUT + n0;
                if (has2 && vec2) *(float2*)p = make_float2(acc[mt][nt][2] + bx, acc[mt][nt][3] + by);
                else { p[0] = acc[mt][nt][2] + bx; if (has2) p[1] = acc[mt][nt][3] + by; }
            }
        }
    }
}

// ---------------- generic single-tile mma GEMM (layers + small heads) ----------------
// A-lo tile no longer needed: only A-hi, B-hi, B-lo (3 tiles)
__global__ __launch_bounds__(256) void mma_gemm_kernel(
    const __half* __restrict__ AH,
    const __half* __restrict__ BH, const __half* __restrict__ BL,
    const float* __restrict__ bias, float* __restrict__ outp, int M, int NOUT)
{
    extern __shared__ char smem[];
    char* sAh = smem;
    char* sBh = smem + TILE_BYTES;
    char* sBl = smem + 2 * TILE_BYTES;
    const int tid = threadIdx.x, wid = tid >> 5, lane = tid & 31;
    const int bm = blockIdx.y * 128;
    const int bn = blockIdx.x * 128;
    load_tile_f16(sAh, AH, bm, M, tid);
    load_tile_f16(sBh, BH, bn, NOUT, tid);
    load_tile_f16(sBl, BL, bn, NOUT, tid);
    __syncthreads();
    mma_tile_compute_store(smem_u32(sAh), smem_u32(sBh), smem_u32(sBl),
                           bias, outp, bm, bn, M, NOUT, wid, lane);
}

// ---------------- author head: B-resident, cp.async double-buffered A ----------------
// smem: B hi/lo (2 tiles) + 2 A-hi buffers = 4 tiles = 139KB
#define ASM_TOTAL (4 * TILE_BYTES)

__global__ __launch_bounds__(256) void author_mma_kernel(
    const __half* __restrict__ AH,
    const __half* __restrict__ BH, const __half* __restrict__ BL,
    const float* __restrict__ bias, float* __restrict__ outp, int M, int NOUT)
{
    extern __shared__ char smem[];
    uint32_t sb = smem_u32(smem);
    const int tid = threadIdx.x, wid = tid >> 5, lane = tid & 31;
    const int bn = blockIdx.x * 128;
    const int mt0 = blockIdx.y * MITERS;

    const uint32_t sBh = sb;
    const uint32_t sBl = sb + TILE_BYTES;
    const uint32_t sA0 = sb + 2 * TILE_BYTES;
    const uint32_t sA1 = sb + 3 * TILE_BYTES;

    load_tile_async(sBh, BH, bn, NOUT, tid);
    load_tile_async(sBl, BL, bn, NOUT, tid);
    int bm0 = mt0 * 128;
    if (bm0 < M) load_tile_async(sA0, AH, bm0, M, tid);
    CP_COMMIT();

    int buf = 0;
#pragma unroll 1
    for (int it = 0; it < MITERS; it++) {
        int bm = (mt0 + it) * 128;
        if (bm >= M) break;
        CP_WAIT0();
        __syncthreads();
        int bmn = (mt0 + it + 1) * 128;
        if (it + 1 < MITERS && bmn < M) {
            load_tile_async((buf ^ 1) ? sA1 : sA0, AH, bmn, M, tid);
        }
        CP_COMMIT();
        uint32_t cb = buf ? sA1 : sA0;
        mma_tile_compute_store(cb, sBh, sBl,
                               bias, outp, bm, bn, M, NOUT, wid, lane);
        buf ^= 1;
    }
}

// ---------------- launch ----------------
extern "C" void kernel_launch(void* const* d_in, const int* in_sizes, int n_in,
                              void* d_out, int out_size) {
    const float* x  = (const float*)d_in[0];
    const int*   ei = (const int*)d_in[1];   // [2, NE] int32
    const float* W1 = (const float*)d_in[2];
    const float* b1 = (const float*)d_in[3];
    const float* W2 = (const float*)d_in[4];
    const float* b2 = (const float*)d_in[5];
    const float* Wt = (const float*)d_in[6];
    const float* bt = (const float*)d_in[7];
    const float* Ws = (const float*)d_in[8];
    const float* bs = (const float*)d_in[9];
    const float* Wf = (const float*)d_in[10];
    const float* bfb = (const float*)d_in[11];
    const float* Wa = (const float*)d_in[12];
    const float* ba = (const float*)d_in[13];
    float* out = (float*)d_out;

    float4* h4;
    float* csmall;
    __half *aH, *w1H, *w1L, *w2H, *w2L, *waH, *waL, *wsH, *wsL;
    cudaGetSymbolAddress((void**)&h4, g_h);
    cudaGetSymbolAddress((void**)&csmall, g_Csmall);
    cudaGetSymbolAddress((void**)&aH, g_AH);
    cudaGetSymbolAddress((void**)&w1H, g_W1H);
    cudaGetSymbolAddress((void**)&w1L, g_W1L);
    cudaGetSymbolAddress((void**)&w2H, g_W2H);
    cudaGetSymbolAddress((void**)&w2L, g_W2L);
    cudaGetSymbolAddress((void**)&waH, g_WaH);
    cudaGetSymbolAddress((void**)&waL, g_WaL);
    cudaGetSymbolAddress((void**)&wsH, g_WsmH);
    cudaGetSymbolAddress((void**)&wsL, g_WsmL);

    static cudaStream_t s1;
    static cudaEvent_t evA, evW1, evB, evW2, evWa, evC, evD;
    static bool init0 = false;
    if (!init0) {
        cudaFuncSetAttribute(mma_gemm_kernel,
                             cudaFuncAttributeMaxDynamicSharedMemorySize, 3 * TILE_BYTES);
        cudaFuncSetAttribute(author_mma_kernel,
                             cudaFuncAttributeMaxDynamicSharedMemorySize, ASM_TOTAL);
        cudaStreamCreateWithFlags(&s1, cudaStreamNonBlocking);
        cudaEventCreateWithFlags(&evA,  cudaEventDisableTiming);
        cudaEventCreateWithFlags(&evW1, cudaEventDisableTiming);
        cudaEventCreateWithFlags(&evB,  cudaEventDisableTiming);
        cudaEventCreateWithFlags(&evW2, cudaEventDisableTiming);
        cudaEventCreateWithFlags(&evWa, cudaEventDisableTiming);
        cudaEventCreateWithFlags(&evC,  cudaEventDisableTiming);
        cudaEventCreateWithFlags(&evD,  cudaEventDisableTiming);
        init0 = true;
    }

    // ---- fork: s1 handles W conversions + CSR build ----
    cudaEventRecord(evA, 0);
    cudaStreamWaitEvent(s1, evA, 0);
    convert_W_kernel<<<(128 * 128 + 255) / 256, 256, 0, s1>>>(W1, 128, w1H, w1L);
    cudaEventRecord(evW1, s1);
    zero_cnt_kernel<<<(NN + 255) / 256, 256, 0, s1>>>();
    cnt_accum_kernel<<<(NE + 255) / 256, 256, 0, s1>>>(ei);
    scan1_kernel<<<NBLK, 1024, 0, s1>>>();
    scan2_kernel<<<1, 64, 0, s1>>>();
    scan3_kernel<<<(NN + 255) / 256, 256, 0, s1>>>();
    scatter_edges_kernel<<<(NE + 255) / 256, 256, 0, s1>>>(ei);
    cudaEventRecord(evB, s1);
    convert_W_kernel<<<(128 * 128 + 255) / 256, 256, 0, s1>>>(W2, 128, w2H, w2L);
    cudaEventRecord(evW2, s1);
    convert_W_kernel<<<(NAUTH * 128 + 255) / 256, 256, 0, s1>>>(Wa, NAUTH, waH, waL);
    pack_small_kernel<<<(NSMALL * 128 + 255) / 256, 256, 0, s1>>>(Wt, Ws, Wf);
    cudaEventRecord(evWa, s1);

    const int AGG_BLK = (NN * 32 + 255) / 256;

    // ---- main stream ----
    convert_x_kernel<<<(NN * 32 + 255) / 256, 256>>>(x);
    cudaStreamWaitEvent(0, evW1, 0);
    mma_gemm_kernel<<<dim3(1, MROWS), 256, 3 * TILE_BYTES>>>(aH, w1H, w1L, nullptr,
                                                             (float*)h4, NN, 128);
    cudaStreamWaitEvent(0, evB, 0);
    csr_agg_kernel<1><<<AGG_BLK, 256>>>(b1);

    cudaStreamWaitEvent(0, evW2, 0);
    mma_gemm_kernel<<<dim3(1, MROWS), 256, 3 * TILE_BYTES>>>(aH, w2H, w2L, nullptr,
                                                             (float*)h4, NN, 128);
    csr_agg_kernel<0><<<AGG_BLK, 256>>>(b2);

    // ---- fork: small heads on s1, concurrent with author head ----
    cudaEventRecord(evC, 0);
    cudaStreamWaitEvent(s1, evC, 0);
    mma_gemm_kernel<<<dim3(1, MROWS), 256, 3 * TILE_BYTES, s1>>>(aH, wsH, wsL, nullptr,
                                                                 csmall, NN, NSMALL);
    split_small_kernel<<<(NN * NSMALL + 255) / 256, 256, 0, s1>>>(bt, bs, bfb, out);
    cudaEventRecord(evD, s1);

    // author head (main stream)
    cudaStreamWaitEvent(0, evWa, 0);
    author_mma_kernel<<<dim3(16, GROUPS), 256, ASM_TOTAL>>>(
        aH, waH, waL, ba, out + (size_t)NN * 65, NN, NAUTH);
    cudaStreamWaitEvent(0, evD, 0);
}